// round 3
// baseline (speedup 1.0000x reference)
#include <cuda_runtime.h>

// Problem constants (match reference_code)
#define KS   17
#define HP   256
#define WP   256
#define HI   (HP + KS - 1)   // 272
#define WI   (WP + KS - 1)   // 272
#define BC   12              // B*C = 4*3
#define P    (HP * WP)       // 65536
#define IMG_BC_STRIDE (HI * WI)  // 73984 floats per (b,c) plane

// Tiling:
//   thread: 4 consecutive x-pixels x 2 (b,c) planes
//   block : (16,2,6) = 192 threads -> tile 64x2 px, all 12 bc (z splits bc, 2 each)
//   grid  : (256/64, 256/2) = (4,128) = 512 blocks, 6 warps each
//           -> 3072 warps total ~= 20.7 warps/SM (vs 10.4 in round 2)
// kern slice (75.7 MB) fits in L2 (126 MB): the 6-way bc replication of kern
// reads hits L1/L2; DRAM sees kern exactly once (~82 MB total traffic).

__global__ void __launch_bounds__(192, 4)
blur_kernel(const float* __restrict__ img,
            const float* __restrict__ kernels,
            const int*   __restrict__ idx_p,
            float*       __restrict__ out)
{
    const int x0  = blockIdx.x * 64 + threadIdx.x * 4;  // multiple of 4
    const int y   = blockIdx.y * 2 + threadIdx.y;
    const int bc0 = threadIdx.z * 2;                    // 0,2,...,10
    const int p0  = y * WP + x0;                        // multiple of 4

    const long long kidx = (long long)(*idx_p);
    const float* __restrict__ kern =
        kernels + kidx * (long long)(KS * KS) * (long long)P;

    float acc[2][4];
#pragma unroll
    for (int bc = 0; bc < 2; bc++)
#pragma unroll
        for (int r = 0; r < 4; r++) acc[bc][r] = 0.0f;

#pragma unroll 1
    for (int kh = 0; kh < KS; kh++) {
        // 20-float window per bc, loaded as 5 x LDG.128 (16B aligned)
        const float* __restrict__ irow =
            img + (long long)bc0 * IMG_BC_STRIDE + (long long)(y + kh) * WI + x0;

        float win[2][20];
#pragma unroll
        for (int bc = 0; bc < 2; bc++) {
#pragma unroll
            for (int v = 0; v < 5; v++) {
                const float4 t = *(const float4*)(irow + bc * IMG_BC_STRIDE + v * 4);
                win[bc][v * 4 + 0] = t.x;
                win[bc][v * 4 + 1] = t.y;
                win[bc][v * 4 + 2] = t.z;
                win[bc][v * 4 + 3] = t.w;
            }
        }

        const float4* __restrict__ krow =
            (const float4*)(kern + (long long)kh * KS * P + p0);

#pragma unroll
        for (int kw = 0; kw < KS; kw++) {
            const float4 w = krow[(long long)kw * (P / 4)];
#pragma unroll
            for (int bc = 0; bc < 2; bc++) {
                acc[bc][0] = fmaf(w.x, win[bc][kw + 0], acc[bc][0]);
                acc[bc][1] = fmaf(w.y, win[bc][kw + 1], acc[bc][1]);
                acc[bc][2] = fmaf(w.z, win[bc][kw + 2], acc[bc][2]);
                acc[bc][3] = fmaf(w.w, win[bc][kw + 3], acc[bc][3]);
            }
        }
    }

#pragma unroll
    for (int bc = 0; bc < 2; bc++) {
        *(float4*)(out + (long long)(bc0 + bc) * P + p0) =
            make_float4(acc[bc][0], acc[bc][1], acc[bc][2], acc[bc][3]);
    }
}

extern "C" void kernel_launch(void* const* d_in, const int* in_sizes, int n_in,
                              void* d_out, int out_size)
{
    const float* img     = (const float*)d_in[0];  // (4,3,272,272) f32
    const float* kernels = (const float*)d_in[1];  // (16,1,289,65536) f32
    const int*   idx     = (const int*)d_in[2];    // scalar int32
    float*       out     = (float*)d_out;          // (4,3,256,256) f32

    dim3 block(16, 2, 6);
    dim3 grid(WP / 64, HP / 2);   // (4, 128)
    blur_kernel<<<grid, block>>>(img, kernels, idx, out);
}

// round 4
// speedup vs baseline: 1.0087x; 1.0087x over previous
#include <cuda_runtime.h>
#include <cstdint>

// Problem constants
#define KS   17
#define HP   256
#define WP   256
#define HI   (HP + KS - 1)   // 272
#define WI   (WP + KS - 1)   // 272
#define P    (HP * WP)       // 65536
#define IMG_BC_STRIDE (HI * WI)

// Tiling: thread = 4 px (x) x 2 bc. Block (8,2,6) = 96 thr -> 32x2 px, 12 bc.
// Grid (8,128) = 1024 blocks -> ~6.92 blocks/SM, all co-resident.
#define TX 8
#define TY 2
#define TZ 6
#define NTHREADS (TX * TY * TZ)       // 96
#define TILE_X   (TX * 4)             // 32
#define NSTAGE   4
#define STAGE_FLOATS (KS * TY * TILE_X)   // 17*2*32 = 1088 floats = 4352 B
#define STAGE_OPS (KS * TY * (TILE_X / 4))  // 16B cp.async ops per stage = 272

__device__ __forceinline__ void cp_async16(uint32_t saddr, const void* gptr) {
    asm volatile("cp.async.cg.shared.global [%0], [%1], 16;\n"
                 :: "r"(saddr), "l"(gptr));
}
__device__ __forceinline__ void cp_commit() {
    asm volatile("cp.async.commit_group;\n" ::: "memory");
}
template <int N>
__device__ __forceinline__ void cp_wait() {
    asm volatile("cp.async.wait_group %0;\n" :: "n"(N) : "memory");
}

__global__ void __launch_bounds__(NTHREADS, 7)
blur_kernel(const float* __restrict__ img,
            const float* __restrict__ kernels,
            const int*   __restrict__ idx_p,
            float*       __restrict__ out)
{
    __shared__ float skern[NSTAGE][STAGE_FLOATS];

    const int tx  = threadIdx.x;
    const int ty  = threadIdx.y;
    const int tz  = threadIdx.z;
    const int tid = tx + ty * TX + tz * TX * TY;

    const int x0  = blockIdx.x * TILE_X;     // block px base (x)
    const int y0  = blockIdx.y * TY;         // block px base (y)
    const int xt  = x0 + tx * 4;
    const int y   = y0 + ty;
    const int bc0 = tz * 2;
    const int p0  = y * WP + xt;

    const long long kidx = (long long)(*idx_p);
    // kern origin for this block: tap (0,0), pixel (y0, x0)
    const float* __restrict__ kern_blk =
        kernels + kidx * (long long)(KS * KS) * (long long)P
                + (long long)y0 * WP + x0;

    const uint32_t sbase = (uint32_t)__cvta_generic_to_shared(&skern[0][0]);

    // ---- cp.async fill of one stage (kern row kh) ----
    // op o: kw = o>>4, yy = (o>>3)&1, seg = o&7
    // smem  : skern[s][(kw*TY + yy)*TILE_X + seg*4]
    // global: kern_blk + (kh*KS + kw)*P + yy*WP + seg*4
    auto fill_stage = [&](int s, int kh) {
#pragma unroll
        for (int o = tid; o < STAGE_OPS; o += NTHREADS) {
            const int kw  = o >> 4;
            const int yy  = (o >> 3) & 1;
            const int seg = o & 7;
            const uint32_t soff =
                (uint32_t)(s * STAGE_FLOATS + (kw * TY + yy) * TILE_X + seg * 4) * 4u;
            const float* g = kern_blk + (long long)(kh * KS + kw) * P + yy * WP + seg * 4;
            cp_async16(sbase + soff, g);
        }
    };

    float acc[2][4];
#pragma unroll
    for (int bc = 0; bc < 2; bc++)
#pragma unroll
        for (int r = 0; r < 4; r++) acc[bc][r] = 0.0f;

    // prologue: stages 0..2 in flight
    fill_stage(0, 0); cp_commit();
    fill_stage(1, 1); cp_commit();
    fill_stage(2, 2); cp_commit();

#pragma unroll 1
    for (int kh = 0; kh < KS; kh++) {
        cp_wait<2>();          // stage kh's group complete (3 groups always in flight)
        __syncthreads();

        // img window for this kh: 20 floats per bc as 5 x LDG.128 (L2-resident)
        const float* __restrict__ irow =
            img + (long long)bc0 * IMG_BC_STRIDE + (long long)(y + kh) * WI + xt;
        float win[2][20];
#pragma unroll
        for (int bc = 0; bc < 2; bc++) {
#pragma unroll
            for (int v = 0; v < 5; v++) {
                const float4 t = *(const float4*)(irow + bc * IMG_BC_STRIDE + v * 4);
                win[bc][v * 4 + 0] = t.x;
                win[bc][v * 4 + 1] = t.y;
                win[bc][v * 4 + 2] = t.z;
                win[bc][v * 4 + 3] = t.w;
            }
        }

        const int st = kh & (NSTAGE - 1);
        const float* __restrict__ srow = &skern[st][ty * TILE_X + tx * 4];

#pragma unroll
        for (int kw = 0; kw < KS; kw++) {
            const float4 w = *(const float4*)(srow + kw * (TY * TILE_X));
#pragma unroll
            for (int bc = 0; bc < 2; bc++) {
                acc[bc][0] = fmaf(w.x, win[bc][kw + 0], acc[bc][0]);
                acc[bc][1] = fmaf(w.y, win[bc][kw + 1], acc[bc][1]);
                acc[bc][2] = fmaf(w.z, win[bc][kw + 2], acc[bc][2]);
                acc[bc][3] = fmaf(w.w, win[bc][kw + 3], acc[bc][3]);
            }
        }

        __syncthreads();       // all warps done reading stage st before refill

        if (kh + NSTAGE - 1 < KS)
            fill_stage((kh + NSTAGE - 1) & (NSTAGE - 1), kh + NSTAGE - 1);
        cp_commit();           // unconditional: keeps group count uniform
    }

#pragma unroll
    for (int bc = 0; bc < 2; bc++) {
        *(float4*)(out + (long long)(bc0 + bc) * P + p0) =
            make_float4(acc[bc][0], acc[bc][1], acc[bc][2], acc[bc][3]);
    }
}

extern "C" void kernel_launch(void* const* d_in, const int* in_sizes, int n_in,
                              void* d_out, int out_size)
{
    const float* img     = (const float*)d_in[0];  // (4,3,272,272) f32
    const float* kernels = (const float*)d_in[1];  // (16,1,289,65536) f32
    const int*   idx     = (const int*)d_in[2];    // scalar int32
    float*       out     = (float*)d_out;          // (4,3,256,256) f32

    dim3 block(TX, TY, TZ);                 // (8,2,6) = 96
    dim3 grid(WP / TILE_X, HP / TY);        // (8,128) = 1024
    blur_kernel<<<grid, block>>>(img, kernels, idx, out);
}